// round 5
// baseline (speedup 1.0000x reference)
#include <cuda_runtime.h>
#include <math.h>

#define N_NODESK 50000
#define N_EDGESK 800000
#define F_INK    128
#define C1K      256     // HEADS*HID
#define HEADSK   8
#define NBLK_SCAN 196    // ceil(50000/256)
#define FULLMASK 0xffffffffu

// ---------------- scratch (device globals: allocation-free contract) ----------------
__device__ float g_h1[N_NODESK * C1K];     // x @ W1 (51.2 MB)
__device__ float g_as1[N_NODESK * HEADSK];
__device__ float g_ad1[N_NODESK * HEADSK];
__device__ float g_h2[N_NODESK * 2];
__device__ float g_as2[N_NODESK];
__device__ float g_ad2[N_NODESK];
__device__ int   g_cnt[N_NODESK];
__device__ int   g_rowptr[N_NODESK + 1];
__device__ int   g_cursor[N_NODESK];
__device__ int   g_col[N_EDGESK];          // src ids grouped by dst
__device__ int   g_bsum[NBLK_SCAN];
__device__ int   g_boff[NBLK_SCAN];

// ---------------- CSR build ----------------
__global__ void zero_cnt_kernel() {
    int i = blockIdx.x * blockDim.x + threadIdx.x;
    if (i < N_NODESK) g_cnt[i] = 0;
}

__global__ void hist_kernel(const int* __restrict__ dst) {
    int e = blockIdx.x * blockDim.x + threadIdx.x;
    if (e < N_EDGESK) atomicAdd(&g_cnt[dst[e]], 1);
}

__global__ void blocksum_kernel() {
    int i = blockIdx.x * 256 + threadIdx.x;
    int v = (i < N_NODESK) ? g_cnt[i] : 0;
    __shared__ int ws[8];
    int lane = threadIdx.x & 31, w = threadIdx.x >> 5;
#pragma unroll
    for (int o = 16; o; o >>= 1) v += __shfl_xor_sync(FULLMASK, v, o);
    if (lane == 0) ws[w] = v;
    __syncthreads();
    if (threadIdx.x == 0) {
        int s = 0;
#pragma unroll
        for (int k = 0; k < 8; k++) s += ws[k];
        g_bsum[blockIdx.x] = s;
    }
}

__global__ void scantop_kernel() {
    __shared__ int sh[256];
    int v = (threadIdx.x < NBLK_SCAN) ? g_bsum[threadIdx.x] : 0;
    sh[threadIdx.x] = v;
    __syncthreads();
    for (int off = 1; off < 256; off <<= 1) {
        int t = (threadIdx.x >= off) ? sh[threadIdx.x - off] : 0;
        __syncthreads();
        sh[threadIdx.x] += t;
        __syncthreads();
    }
    if (threadIdx.x < NBLK_SCAN) g_boff[threadIdx.x] = sh[threadIdx.x] - v;
}

__global__ void scanlocal_kernel() {
    __shared__ int sh[256];
    int i = blockIdx.x * 256 + threadIdx.x;
    int v = (i < N_NODESK) ? g_cnt[i] : 0;
    sh[threadIdx.x] = v;
    __syncthreads();
    for (int off = 1; off < 256; off <<= 1) {
        int t = (threadIdx.x >= off) ? sh[threadIdx.x - off] : 0;
        __syncthreads();
        sh[threadIdx.x] += t;
        __syncthreads();
    }
    int incl = sh[threadIdx.x];
    int base = g_boff[blockIdx.x];
    if (i < N_NODESK) {
        int excl = base + incl - v;
        g_rowptr[i] = excl;
        g_cursor[i] = excl;
        if (i == N_NODESK - 1) g_rowptr[N_NODESK] = base + incl;
    }
}

__global__ void scatter_kernel(const int* __restrict__ src, const int* __restrict__ dst) {
    int e = blockIdx.x * blockDim.x + threadIdx.x;
    if (e < N_EDGESK) {
        int pos = atomicAdd(&g_cursor[dst[e]], 1);
        g_col[pos] = src[e];
    }
}

// ---------------- SGEMM: g_h1 = x[M,128] @ W1[128,256] ----------------
__global__ __launch_bounds__(256) void sgemm_kernel(const float* __restrict__ A,
                                                    const float* __restrict__ B) {
    __shared__ float As[2][16][128];
    __shared__ float Bs[2][16][128];
    const int tid = threadIdx.x;
    const int bm = blockIdx.y * 128;
    const int bn = blockIdx.x * 128;
    const int tx = tid & 15, ty = tid >> 4;

    const int arow = tid >> 2;
    const int akc  = tid & 3;
    const int bkr  = tid >> 5;
    const int bcc  = tid & 31;

    float acc[8][8];
#pragma unroll
    for (int i = 0; i < 8; i++)
#pragma unroll
        for (int j = 0; j < 8; j++) acc[i][j] = 0.f;

    float4 aR0, aR1, bR0, bR1;
    const float4 z4 = make_float4(0.f, 0.f, 0.f, 0.f);
    {
        int r0 = bm + arow, r1 = bm + arow + 64;
        aR0 = (r0 < N_NODESK) ? *(const float4*)(A + (size_t)r0 * F_INK + akc * 4) : z4;
        aR1 = (r1 < N_NODESK) ? *(const float4*)(A + (size_t)r1 * F_INK + akc * 4) : z4;
        bR0 = *(const float4*)(B + (size_t)bkr * C1K + bn + bcc * 4);
        bR1 = *(const float4*)(B + (size_t)(bkr + 8) * C1K + bn + bcc * 4);
    }
    As[0][akc * 4 + 0][arow] = aR0.x; As[0][akc * 4 + 1][arow] = aR0.y;
    As[0][akc * 4 + 2][arow] = aR0.z; As[0][akc * 4 + 3][arow] = aR0.w;
    As[0][akc * 4 + 0][arow + 64] = aR1.x; As[0][akc * 4 + 1][arow + 64] = aR1.y;
    As[0][akc * 4 + 2][arow + 64] = aR1.z; As[0][akc * 4 + 3][arow + 64] = aR1.w;
    *(float4*)&Bs[0][bkr][bcc * 4] = bR0;
    *(float4*)&Bs[0][bkr + 8][bcc * 4] = bR1;
    __syncthreads();

    int buf = 0;
#pragma unroll
    for (int t = 0; t < 8; ++t) {
        if (t < 7) {
            int kt = (t + 1) * 16;
            int r0 = bm + arow, r1 = bm + arow + 64;
            aR0 = (r0 < N_NODESK) ? *(const float4*)(A + (size_t)r0 * F_INK + kt + akc * 4) : z4;
            aR1 = (r1 < N_NODESK) ? *(const float4*)(A + (size_t)r1 * F_INK + kt + akc * 4) : z4;
            bR0 = *(const float4*)(B + (size_t)(kt + bkr) * C1K + bn + bcc * 4);
            bR1 = *(const float4*)(B + (size_t)(kt + bkr + 8) * C1K + bn + bcc * 4);
        }
#pragma unroll
        for (int k = 0; k < 16; ++k) {
            float4 a0 = *(const float4*)&As[buf][k][ty * 8];
            float4 a1 = *(const float4*)&As[buf][k][ty * 8 + 4];
            float4 b0 = *(const float4*)&Bs[buf][k][tx * 8];
            float4 b1 = *(const float4*)&Bs[buf][k][tx * 8 + 4];
            float av[8] = {a0.x, a0.y, a0.z, a0.w, a1.x, a1.y, a1.z, a1.w};
            float bv[8] = {b0.x, b0.y, b0.z, b0.w, b1.x, b1.y, b1.z, b1.w};
#pragma unroll
            for (int i = 0; i < 8; i++)
#pragma unroll
                for (int j = 0; j < 8; j++) acc[i][j] += av[i] * bv[j];
        }
        if (t < 7) {
            int nb = buf ^ 1;
            As[nb][akc * 4 + 0][arow] = aR0.x; As[nb][akc * 4 + 1][arow] = aR0.y;
            As[nb][akc * 4 + 2][arow] = aR0.z; As[nb][akc * 4 + 3][arow] = aR0.w;
            As[nb][akc * 4 + 0][arow + 64] = aR1.x; As[nb][akc * 4 + 1][arow + 64] = aR1.y;
            As[nb][akc * 4 + 2][arow + 64] = aR1.z; As[nb][akc * 4 + 3][arow + 64] = aR1.w;
            *(float4*)&Bs[nb][bkr][bcc * 4] = bR0;
            *(float4*)&Bs[nb][bkr + 8][bcc * 4] = bR1;
            __syncthreads();
            buf = nb;
        }
    }
#pragma unroll
    for (int i = 0; i < 8; i++) {
        int r = bm + ty * 8 + i;
        if (r < N_NODESK) {
            float4 o0 = make_float4(acc[i][0], acc[i][1], acc[i][2], acc[i][3]);
            float4 o1 = make_float4(acc[i][4], acc[i][5], acc[i][6], acc[i][7]);
            *(float4*)(g_h1 + (size_t)r * C1K + bn + tx * 8) = o0;
            *(float4*)(g_h1 + (size_t)r * C1K + bn + tx * 8 + 4) = o1;
        }
    }
}

// ---------------- alpha1 ----------------
__global__ void alpha1_kernel(const float* __restrict__ a_src, const float* __restrict__ a_dst) {
    int t = blockIdx.x * blockDim.x + threadIdx.x;
    if (t >= N_NODESK * HEADSK) return;
    int n = t >> 3, h = t & 7;
    const float4* hr = (const float4*)(g_h1 + (size_t)n * C1K + h * 32);
    const float4* av = (const float4*)(a_src + h * 32);
    const float4* bv = (const float4*)(a_dst + h * 32);
    float s = 0.f, d = 0.f;
#pragma unroll
    for (int i = 0; i < 8; i++) {
        float4 v = hr[i];
        float4 a = av[i];
        float4 b = bv[i];
        s += v.x * a.x + v.y * a.y + v.z * a.z + v.w * a.w;
        d += v.x * b.x + v.y * b.y + v.z * b.z + v.w * b.w;
    }
    g_as1[t] = s;
    g_ad1[t] = d;
}

__device__ __forceinline__ float lrelu02(float x) { return x > 0.f ? x : 0.2f * x; }
__device__ __forceinline__ float eluf(float x)    { return x > 0.f ? x : expm1f(x); }

// ---------------- layer-1 aggregation (quad-edge, exp-dedup) fused with layer-2 transform --
// warp per dst node. lane l owns channels [4l,4l+3] (head l/8) and [128+4l,128+4l+3].
// Quad step: lane group g=lane>>3 evaluates edge e+g; one __expf covers 4 edges x 8 heads.
__global__ __launch_bounds__(256) void agg1_kernel(const float* __restrict__ b1,
                                                   const float* __restrict__ W2,
                                                   const float* __restrict__ a2s,
                                                   const float* __restrict__ a2d) {
    int warp = (blockIdx.x * blockDim.x + threadIdx.x) >> 5;
    int lane = threadIdx.x & 31;
    if (warp >= N_NODESK) return;
    const int n = warp;
    const int hA = lane >> 3;       // 0..3
    const int hB = 4 + hA;
    const int l7 = lane & 7;
    const int grp = lane >> 3;      // edge slot in quad step
    const float ad8 = g_ad1[n * 8 + l7];

    float4 accA = make_float4(0.f, 0.f, 0.f, 0.f);
    float4 accB = make_float4(0.f, 0.f, 0.f, 0.f);
    float denA = 0.f, denB = 0.f;

    const int beg = g_rowptr[n], end = g_rowptr[n + 1];

    // self loop
    {
        float w = __expf(lrelu02(g_as1[n * 8 + l7] + ad8));
        float wA = __shfl_sync(FULLMASK, w, hA);
        float wB = __shfl_sync(FULLMASK, w, hB);
        const float4* row = (const float4*)(g_h1 + (size_t)n * C1K);
        float4 vA = row[lane], vB = row[32 + lane];
        accA.x += wA * vA.x; accA.y += wA * vA.y; accA.z += wA * vA.z; accA.w += wA * vA.w;
        accB.x += wB * vB.x; accB.y += wB * vB.y; accB.z += wB * vB.z; accB.w += wB * vB.w;
        denA += wA; denB += wB;
    }

    int e = beg;
    for (; e + 4 <= end; e += 4) {
        int ss = g_col[e + grp];                     // each 8-lane group owns one edge
        float w = __expf(lrelu02(g_as1[ss * 8 + l7] + ad8));
#pragma unroll
        for (int j = 0; j < 4; ++j) {
            int  sj = __shfl_sync(FULLMASK, ss, j * 8);
            float wA = __shfl_sync(FULLMASK, w, j * 8 + hA);
            float wB = __shfl_sync(FULLMASK, w, j * 8 + hB);
            const float4* row = (const float4*)(g_h1 + (size_t)sj * C1K);
            float4 vA = row[lane], vB = row[32 + lane];
            accA.x += wA * vA.x; accA.y += wA * vA.y; accA.z += wA * vA.z; accA.w += wA * vA.w;
            accB.x += wB * vB.x; accB.y += wB * vB.y; accB.z += wB * vB.z; accB.w += wB * vB.w;
            denA += wA; denB += wB;
        }
    }
    for (; e < end; ++e) {
        int s = g_col[e];
        float w = __expf(lrelu02(g_as1[s * 8 + l7] + ad8));
        float wA = __shfl_sync(FULLMASK, w, hA);
        float wB = __shfl_sync(FULLMASK, w, hB);
        const float4* row = (const float4*)(g_h1 + (size_t)s * C1K);
        float4 vA = row[lane], vB = row[32 + lane];
        accA.x += wA * vA.x; accA.y += wA * vA.y; accA.z += wA * vA.z; accA.w += wA * vA.w;
        accB.x += wB * vB.x; accB.y += wB * vB.y; accB.z += wB * vB.z; accB.w += wB * vB.w;
        denA += wA; denB += wB;
    }

    float rA = 1.f / denA, rB = 1.f / denB;
    const float4 bA = *(const float4*)(b1 + 4 * lane);
    const float4 bB = *(const float4*)(b1 + 128 + 4 * lane);
    float4 oA, oB;
    oA.x = eluf(accA.x * rA + bA.x); oA.y = eluf(accA.y * rA + bA.y);
    oA.z = eluf(accA.z * rA + bA.z); oA.w = eluf(accA.w * rA + bA.w);
    oB.x = eluf(accB.x * rB + bB.x); oB.y = eluf(accB.y * rB + bB.y);
    oB.z = eluf(accB.z * rB + bB.z); oB.w = eluf(accB.w * rB + bB.w);

    // layer-2 node transform (hout never materialized)
    int cA = 4 * lane, cB = 128 + 4 * lane;
    float acc0 = oA.x * W2[(cA + 0) * 2] + oA.y * W2[(cA + 1) * 2]
               + oA.z * W2[(cA + 2) * 2] + oA.w * W2[(cA + 3) * 2]
               + oB.x * W2[(cB + 0) * 2] + oB.y * W2[(cB + 1) * 2]
               + oB.z * W2[(cB + 2) * 2] + oB.w * W2[(cB + 3) * 2];
    float acc1 = oA.x * W2[(cA + 0) * 2 + 1] + oA.y * W2[(cA + 1) * 2 + 1]
               + oA.z * W2[(cA + 2) * 2 + 1] + oA.w * W2[(cA + 3) * 2 + 1]
               + oB.x * W2[(cB + 0) * 2 + 1] + oB.y * W2[(cB + 1) * 2 + 1]
               + oB.z * W2[(cB + 2) * 2 + 1] + oB.w * W2[(cB + 3) * 2 + 1];
#pragma unroll
    for (int o = 16; o; o >>= 1) {
        acc0 += __shfl_xor_sync(FULLMASK, acc0, o);
        acc1 += __shfl_xor_sync(FULLMASK, acc1, o);
    }
    if (lane == 0) {
        g_h2[n * 2 + 0] = acc0;
        g_h2[n * 2 + 1] = acc1;
        g_as2[n] = acc0 * a2s[0] + acc1 * a2s[1];
        g_ad2[n] = acc0 * a2d[0] + acc1 * a2d[1];
    }
}

// ---------------- layer-2 aggregation: warp per dst node (edge-parallel) ----------------
__global__ __launch_bounds__(256) void agg2_kernel(const float* __restrict__ b2,
                                                   float* __restrict__ out) {
    int warp = (blockIdx.x * blockDim.x + threadIdx.x) >> 5;
    int lane = threadIdx.x & 31;
    if (warp >= N_NODESK) return;
    const int n = warp;
    float adn = g_ad2[n];
    int beg = g_rowptr[n], end = g_rowptr[n + 1];
    float den = 0.f, o0 = 0.f, o1 = 0.f;
    for (int e = beg + lane; e < end; e += 32) {
        int s = g_col[e];
        float w = __expf(lrelu02(g_as2[s] + adn));
        den += w;
        o0 += w * g_h2[s * 2 + 0];
        o1 += w * g_h2[s * 2 + 1];
    }
    if (lane == 0) {    // self loop
        float w = __expf(lrelu02(g_as2[n] + adn));
        den += w;
        o0 += w * g_h2[n * 2 + 0];
        o1 += w * g_h2[n * 2 + 1];
    }
#pragma unroll
    for (int o = 16; o; o >>= 1) {
        den += __shfl_xor_sync(FULLMASK, den, o);
        o0  += __shfl_xor_sync(FULLMASK, o0, o);
        o1  += __shfl_xor_sync(FULLMASK, o1, o);
    }
    if (lane == 0) {
        float r = 1.f / den;
        out[n * 2 + 0] = o0 * r + b2[0];
        out[n * 2 + 1] = o1 * r + b2[1];
    }
}

// ---------------- launch ----------------
extern "C" void kernel_launch(void* const* d_in, const int* in_sizes, int n_in,
                              void* d_out, int out_size) {
    const float* x    = (const float*)d_in[0];
    const int*   ei   = (const int*)d_in[1];
    const float* W1   = (const float*)d_in[3];
    const float* a1s  = (const float*)d_in[4];
    const float* a1d  = (const float*)d_in[5];
    const float* b1   = (const float*)d_in[6];
    const float* W2   = (const float*)d_in[7];
    const float* a2s  = (const float*)d_in[8];
    const float* a2d  = (const float*)d_in[9];
    const float* b2   = (const float*)d_in[10];
    float* out = (float*)d_out;

    const int* src = ei;
    const int* dst = ei + N_EDGESK;

    // sgemm placed 4th so the profiler's captured launch is the GEMM.
    zero_cnt_kernel<<<(N_NODESK + 255) / 256, 256>>>();
    hist_kernel<<<(N_EDGESK + 255) / 256, 256>>>(dst);
    blocksum_kernel<<<NBLK_SCAN, 256>>>();
    sgemm_kernel<<<dim3(C1K / 128, (N_NODESK + 127) / 128), 256>>>(x, W1);
    scantop_kernel<<<1, 256>>>();
    scanlocal_kernel<<<NBLK_SCAN, 256>>>();
    scatter_kernel<<<(N_EDGESK + 255) / 256, 256>>>(src, dst);

    alpha1_kernel<<<(N_NODESK * HEADSK + 255) / 256, 256>>>(a1s, a1d);
    agg1_kernel<<<(N_NODESK * 32 + 255) / 256, 256>>>(b1, W2, a2s, a2d);
    agg2_kernel<<<(N_NODESK * 32 + 255) / 256, 256>>>(b2, out);
}

// round 8
// speedup vs baseline: 1.0046x; 1.0046x over previous
#include <cuda_runtime.h>
#include <math.h>

#define N_NODESK 50000
#define N_EDGESK 800000
#define F_INK    128
#define C1K      256     // HEADS*HID
#define HEADSK   8
#define NBLK_SCAN 196    // ceil(50000/256)
#define FULLMASK 0xffffffffu

// ---------------- scratch (device globals: allocation-free contract) ----------------
__device__ float g_h1[N_NODESK * C1K];     // x @ W1 (51.2 MB)
__device__ float g_as1[N_NODESK * HEADSK];
__device__ float g_ad1[N_NODESK * HEADSK];
__device__ float g_h2[N_NODESK * 2];
__device__ float g_as2[N_NODESK];
__device__ float g_ad2[N_NODESK];
__device__ int   g_cnt[N_NODESK];
__device__ int   g_rowptr[N_NODESK + 1];
__device__ int   g_cursor[N_NODESK];
__device__ int   g_col[N_EDGESK];          // src ids grouped by dst
__device__ int   g_bsum[NBLK_SCAN];
__device__ int   g_boff[NBLK_SCAN];

// ---------------- CSR build ----------------
__global__ void zero_cnt_kernel() {
    int i = blockIdx.x * blockDim.x + threadIdx.x;
    if (i < N_NODESK) g_cnt[i] = 0;
}

__global__ void hist_kernel(const int* __restrict__ dst) {
    int e = blockIdx.x * blockDim.x + threadIdx.x;
    if (e < N_EDGESK) atomicAdd(&g_cnt[dst[e]], 1);
}

__global__ void blocksum_kernel() {
    int i = blockIdx.x * 256 + threadIdx.x;
    int v = (i < N_NODESK) ? g_cnt[i] : 0;
    __shared__ int ws[8];
    int lane = threadIdx.x & 31, w = threadIdx.x >> 5;
#pragma unroll
    for (int o = 16; o; o >>= 1) v += __shfl_xor_sync(FULLMASK, v, o);
    if (lane == 0) ws[w] = v;
    __syncthreads();
    if (threadIdx.x == 0) {
        int s = 0;
#pragma unroll
        for (int k = 0; k < 8; k++) s += ws[k];
        g_bsum[blockIdx.x] = s;
    }
}

__global__ void scantop_kernel() {
    __shared__ int sh[256];
    int v = (threadIdx.x < NBLK_SCAN) ? g_bsum[threadIdx.x] : 0;
    sh[threadIdx.x] = v;
    __syncthreads();
    for (int off = 1; off < 256; off <<= 1) {
        int t = (threadIdx.x >= off) ? sh[threadIdx.x - off] : 0;
        __syncthreads();
        sh[threadIdx.x] += t;
        __syncthreads();
    }
    if (threadIdx.x < NBLK_SCAN) g_boff[threadIdx.x] = sh[threadIdx.x] - v;
}

__global__ void scanlocal_kernel() {
    __shared__ int sh[256];
    int i = blockIdx.x * 256 + threadIdx.x;
    int v = (i < N_NODESK) ? g_cnt[i] : 0;
    sh[threadIdx.x] = v;
    __syncthreads();
    for (int off = 1; off < 256; off <<= 1) {
        int t = (threadIdx.x >= off) ? sh[threadIdx.x - off] : 0;
        __syncthreads();
        sh[threadIdx.x] += t;
        __syncthreads();
    }
    int incl = sh[threadIdx.x];
    int base = g_boff[blockIdx.x];
    if (i < N_NODESK) {
        int excl = base + incl - v;
        g_rowptr[i] = excl;
        g_cursor[i] = excl;
        if (i == N_NODESK - 1) g_rowptr[N_NODESK] = base + incl;
    }
}

__global__ void scatter_kernel(const int* __restrict__ src, const int* __restrict__ dst) {
    int e = blockIdx.x * blockDim.x + threadIdx.x;
    if (e < N_EDGESK) {
        int pos = atomicAdd(&g_cursor[dst[e]], 1);
        g_col[pos] = src[e];
    }
}

// ---------------- SGEMM: g_h1 = x[M,128] @ W1[128,256] ----------------
__global__ __launch_bounds__(256) void sgemm_kernel(const float* __restrict__ A,
                                                    const float* __restrict__ B) {
    __shared__ float As[2][16][128];
    __shared__ float Bs[2][16][128];
    const int tid = threadIdx.x;
    const int bm = blockIdx.y * 128;
    const int bn = blockIdx.x * 128;
    const int tx = tid & 15, ty = tid >> 4;

    const int arow = tid >> 2;
    const int akc  = tid & 3;
    const int bkr  = tid >> 5;
    const int bcc  = tid & 31;

    float acc[8][8];
#pragma unroll
    for (int i = 0; i < 8; i++)
#pragma unroll
        for (int j = 0; j < 8; j++) acc[i][j] = 0.f;

    float4 aR0, aR1, bR0, bR1;
    const float4 z4 = make_float4(0.f, 0.f, 0.f, 0.f);
    {
        int r0 = bm + arow, r1 = bm + arow + 64;
        aR0 = (r0 < N_NODESK) ? *(const float4*)(A + (size_t)r0 * F_INK + akc * 4) : z4;
        aR1 = (r1 < N_NODESK) ? *(const float4*)(A + (size_t)r1 * F_INK + akc * 4) : z4;
        bR0 = *(const float4*)(B + (size_t)bkr * C1K + bn + bcc * 4);
        bR1 = *(const float4*)(B + (size_t)(bkr + 8) * C1K + bn + bcc * 4);
    }
    As[0][akc * 4 + 0][arow] = aR0.x; As[0][akc * 4 + 1][arow] = aR0.y;
    As[0][akc * 4 + 2][arow] = aR0.z; As[0][akc * 4 + 3][arow] = aR0.w;
    As[0][akc * 4 + 0][arow + 64] = aR1.x; As[0][akc * 4 + 1][arow + 64] = aR1.y;
    As[0][akc * 4 + 2][arow + 64] = aR1.z; As[0][akc * 4 + 3][arow + 64] = aR1.w;
    *(float4*)&Bs[0][bkr][bcc * 4] = bR0;
    *(float4*)&Bs[0][bkr + 8][bcc * 4] = bR1;
    __syncthreads();

    int buf = 0;
#pragma unroll
    for (int t = 0; t < 8; ++t) {
        if (t < 7) {
            int kt = (t + 1) * 16;
            int r0 = bm + arow, r1 = bm + arow + 64;
            aR0 = (r0 < N_NODESK) ? *(const float4*)(A + (size_t)r0 * F_INK + kt + akc * 4) : z4;
            aR1 = (r1 < N_NODESK) ? *(const float4*)(A + (size_t)r1 * F_INK + kt + akc * 4) : z4;
            bR0 = *(const float4*)(B + (size_t)(kt + bkr) * C1K + bn + bcc * 4);
            bR1 = *(const float4*)(B + (size_t)(kt + bkr + 8) * C1K + bn + bcc * 4);
        }
#pragma unroll
        for (int k = 0; k < 16; ++k) {
            float4 a0 = *(const float4*)&As[buf][k][ty * 8];
            float4 a1 = *(const float4*)&As[buf][k][ty * 8 + 4];
            float4 b0 = *(const float4*)&Bs[buf][k][tx * 8];
            float4 b1 = *(const float4*)&Bs[buf][k][tx * 8 + 4];
            float av[8] = {a0.x, a0.y, a0.z, a0.w, a1.x, a1.y, a1.z, a1.w};
            float bv[8] = {b0.x, b0.y, b0.z, b0.w, b1.x, b1.y, b1.z, b1.w};
#pragma unroll
            for (int i = 0; i < 8; i++)
#pragma unroll
                for (int j = 0; j < 8; j++) acc[i][j] += av[i] * bv[j];
        }
        if (t < 7) {
            int nb = buf ^ 1;
            As[nb][akc * 4 + 0][arow] = aR0.x; As[nb][akc * 4 + 1][arow] = aR0.y;
            As[nb][akc * 4 + 2][arow] = aR0.z; As[nb][akc * 4 + 3][arow] = aR0.w;
            As[nb][akc * 4 + 0][arow + 64] = aR1.x; As[nb][akc * 4 + 1][arow + 64] = aR1.y;
            As[nb][akc * 4 + 2][arow + 64] = aR1.z; As[nb][akc * 4 + 3][arow + 64] = aR1.w;
            *(float4*)&Bs[nb][bkr][bcc * 4] = bR0;
            *(float4*)&Bs[nb][bkr + 8][bcc * 4] = bR1;
            __syncthreads();
            buf = nb;
        }
    }
#pragma unroll
    for (int i = 0; i < 8; i++) {
        int r = bm + ty * 8 + i;
        if (r < N_NODESK) {
            float4 o0 = make_float4(acc[i][0], acc[i][1], acc[i][2], acc[i][3]);
            float4 o1 = make_float4(acc[i][4], acc[i][5], acc[i][6], acc[i][7]);
            *(float4*)(g_h1 + (size_t)r * C1K + bn + tx * 8) = o0;
            *(float4*)(g_h1 + (size_t)r * C1K + bn + tx * 8 + 4) = o1;
        }
    }
}

// ---------------- alpha1 ----------------
__global__ void alpha1_kernel(const float* __restrict__ a_src, const float* __restrict__ a_dst) {
    int t = blockIdx.x * blockDim.x + threadIdx.x;
    if (t >= N_NODESK * HEADSK) return;
    int n = t >> 3, h = t & 7;
    const float4* hr = (const float4*)(g_h1 + (size_t)n * C1K + h * 32);
    const float4* av = (const float4*)(a_src + h * 32);
    const float4* bv = (const float4*)(a_dst + h * 32);
    float s = 0.f, d = 0.f;
#pragma unroll
    for (int i = 0; i < 8; i++) {
        float4 v = hr[i];
        float4 a = av[i];
        float4 b = bv[i];
        s += v.x * a.x + v.y * a.y + v.z * a.z + v.w * a.w;
        d += v.x * b.x + v.y * b.y + v.z * b.z + v.w * b.w;
    }
    g_as1[t] = s;
    g_ad1[t] = d;
}

__device__ __forceinline__ float lrelu02(float x) { return x > 0.f ? x : 0.2f * x; }
__device__ __forceinline__ float eluf(float x)    { return x > 0.f ? x : expm1f(x); }

// ---------------- layer-1 aggregation (quad-edge, exp-dedup) fused with layer-2 transform --
// warp per dst node. lane l owns channels [4l,4l+3] (head l/8) and [128+4l,128+4l+3].
// Quad step: lane group g=lane>>3 evaluates edge e+g; one __expf covers 4 edges x 8 heads.
__global__ __launch_bounds__(256) void agg1_kernel(const float* __restrict__ b1,
                                                   const float* __restrict__ W2,
                                                   const float* __restrict__ a2s,
                                                   const float* __restrict__ a2d) {
    int warp = (blockIdx.x * blockDim.x + threadIdx.x) >> 5;
    int lane = threadIdx.x & 31;
    if (warp >= N_NODESK) return;
    const int n = warp;
    const int hA = lane >> 3;       // 0..3
    const int hB = 4 + hA;
    const int l7 = lane & 7;
    const int grp = lane >> 3;      // edge slot in quad step
    const float ad8 = g_ad1[n * 8 + l7];

    float4 accA = make_float4(0.f, 0.f, 0.f, 0.f);
    float4 accB = make_float4(0.f, 0.f, 0.f, 0.f);
    float denA = 0.f, denB = 0.f;

    const int beg = g_rowptr[n], end = g_rowptr[n + 1];

    // self loop
    {
        float w = __expf(lrelu02(g_as1[n * 8 + l7] + ad8));
        float wA = __shfl_sync(FULLMASK, w, hA);
        float wB = __shfl_sync(FULLMASK, w, hB);
        const float4* row = (const float4*)(g_h1 + (size_t)n * C1K);
        float4 vA = row[lane], vB = row[32 + lane];
        accA.x += wA * vA.x; accA.y += wA * vA.y; accA.z += wA * vA.z; accA.w += wA * vA.w;
        accB.x += wB * vB.x; accB.y += wB * vB.y; accB.z += wB * vB.z; accB.w += wB * vB.w;
        denA += wA; denB += wB;
    }

    int e = beg;
    for (; e + 4 <= end; e += 4) {
        int ss = g_col[e + grp];                     // each 8-lane group owns one edge
        float w = __expf(lrelu02(g_as1[ss * 8 + l7] + ad8));
#pragma unroll
        for (int j = 0; j < 4; ++j) {
            int  sj = __shfl_sync(FULLMASK, ss, j * 8);
            float wA = __shfl_sync(FULLMASK, w, j * 8 + hA);
            float wB = __shfl_sync(FULLMASK, w, j * 8 + hB);
            const float4* row = (const float4*)(g_h1 + (size_t)sj * C1K);
            float4 vA = row[lane], vB = row[32 + lane];
            accA.x += wA * vA.x; accA.y += wA * vA.y; accA.z += wA * vA.z; accA.w += wA * vA.w;
            accB.x += wB * vB.x; accB.y += wB * vB.y; accB.z += wB * vB.z; accB.w += wB * vB.w;
            denA += wA; denB += wB;
        }
    }
    for (; e < end; ++e) {
        int s = g_col[e];
        float w = __expf(lrelu02(g_as1[s * 8 + l7] + ad8));
        float wA = __shfl_sync(FULLMASK, w, hA);
        float wB = __shfl_sync(FULLMASK, w, hB);
        const float4* row = (const float4*)(g_h1 + (size_t)s * C1K);
        float4 vA = row[lane], vB = row[32 + lane];
        accA.x += wA * vA.x; accA.y += wA * vA.y; accA.z += wA * vA.z; accA.w += wA * vA.w;
        accB.x += wB * vB.x; accB.y += wB * vB.y; accB.z += wB * vB.z; accB.w += wB * vB.w;
        denA += wA; denB += wB;
    }

    float rA = 1.f / denA, rB = 1.f / denB;
    const float4 bA = *(const float4*)(b1 + 4 * lane);
    const float4 bB = *(const float4*)(b1 + 128 + 4 * lane);
    float4 oA, oB;
    oA.x = eluf(accA.x * rA + bA.x); oA.y = eluf(accA.y * rA + bA.y);
    oA.z = eluf(accA.z * rA + bA.z); oA.w = eluf(accA.w * rA + bA.w);
    oB.x = eluf(accB.x * rB + bB.x); oB.y = eluf(accB.y * rB + bB.y);
    oB.z = eluf(accB.z * rB + bB.z); oB.w = eluf(accB.w * rB + bB.w);

    // layer-2 node transform (hout never materialized)
    int cA = 4 * lane, cB = 128 + 4 * lane;
    float acc0 = oA.x * W2[(cA + 0) * 2] + oA.y * W2[(cA + 1) * 2]
               + oA.z * W2[(cA + 2) * 2] + oA.w * W2[(cA + 3) * 2]
               + oB.x * W2[(cB + 0) * 2] + oB.y * W2[(cB + 1) * 2]
               + oB.z * W2[(cB + 2) * 2] + oB.w * W2[(cB + 3) * 2];
    float acc1 = oA.x * W2[(cA + 0) * 2 + 1] + oA.y * W2[(cA + 1) * 2 + 1]
               + oA.z * W2[(cA + 2) * 2 + 1] + oA.w * W2[(cA + 3) * 2 + 1]
               + oB.x * W2[(cB + 0) * 2 + 1] + oB.y * W2[(cB + 1) * 2 + 1]
               + oB.z * W2[(cB + 2) * 2 + 1] + oB.w * W2[(cB + 3) * 2 + 1];
#pragma unroll
    for (int o = 16; o; o >>= 1) {
        acc0 += __shfl_xor_sync(FULLMASK, acc0, o);
        acc1 += __shfl_xor_sync(FULLMASK, acc1, o);
    }
    if (lane == 0) {
        g_h2[n * 2 + 0] = acc0;
        g_h2[n * 2 + 1] = acc1;
        g_as2[n] = acc0 * a2s[0] + acc1 * a2s[1];
        g_ad2[n] = acc0 * a2d[0] + acc1 * a2d[1];
    }
}

// ---------------- layer-2 aggregation: warp per dst node (edge-parallel) ----------------
__global__ __launch_bounds__(256) void agg2_kernel(const float* __restrict__ b2,
                                                   float* __restrict__ out) {
    int warp = (blockIdx.x * blockDim.x + threadIdx.x) >> 5;
    int lane = threadIdx.x & 31;
    if (warp >= N_NODESK) return;
    const int n = warp;
    float adn = g_ad2[n];
    int beg = g_rowptr[n], end = g_rowptr[n + 1];
    float den = 0.f, o0 = 0.f, o1 = 0.f;
    for (int e = beg + lane; e < end; e += 32) {
        int s = g_col[e];
        float w = __expf(lrelu02(g_as2[s] + adn));
        den += w;
        o0 += w * g_h2[s * 2 + 0];
        o1 += w * g_h2[s * 2 + 1];
    }
    if (lane == 0) {    // self loop
        float w = __expf(lrelu02(g_as2[n] + adn));
        den += w;
        o0 += w * g_h2[n * 2 + 0];
        o1 += w * g_h2[n * 2 + 1];
    }
#pragma unroll
    for (int o = 16; o; o >>= 1) {
        den += __shfl_xor_sync(FULLMASK, den, o);
        o0  += __shfl_xor_sync(FULLMASK, o0, o);
        o1  += __shfl_xor_sync(FULLMASK, o1, o);
    }
    if (lane == 0) {
        float r = 1.f / den;
        out[n * 2 + 0] = o0 * r + b2[0];
        out[n * 2 + 1] = o1 * r + b2[1];
    }
}

// ---------------- launch ----------------
extern "C" void kernel_launch(void* const* d_in, const int* in_sizes, int n_in,
                              void* d_out, int out_size) {
    const float* x    = (const float*)d_in[0];
    const int*   ei   = (const int*)d_in[1];
    const float* W1   = (const float*)d_in[3];
    const float* a1s  = (const float*)d_in[4];
    const float* a1d  = (const float*)d_in[5];
    const float* b1   = (const float*)d_in[6];
    const float* W2   = (const float*)d_in[7];
    const float* a2s  = (const float*)d_in[8];
    const float* a2d  = (const float*)d_in[9];
    const float* b2   = (const float*)d_in[10];
    float* out = (float*)d_out;

    const int* src = ei;
    const int* dst = ei + N_EDGESK;

    // sgemm placed 4th so the profiler's captured launch is the GEMM.
    zero_cnt_kernel<<<(N_NODESK + 255) / 256, 256>>>();
    hist_kernel<<<(N_EDGESK + 255) / 256, 256>>>(dst);
    blocksum_kernel<<<NBLK_SCAN, 256>>>();
    sgemm_kernel<<<dim3(C1K / 128, (N_NODESK + 127) / 128), 256>>>(x, W1);
    scantop_kernel<<<1, 256>>>();
    scanlocal_kernel<<<NBLK_SCAN, 256>>>();
    scatter_kernel<<<(N_EDGESK + 255) / 256, 256>>>(src, dst);

    alpha1_kernel<<<(N_NODESK * HEADSK + 255) / 256, 256>>>(a1s, a1d);
    agg1_kernel<<<(N_NODESK * 32 + 255) / 256, 256>>>(b1, W2, a2s, a2d);
    agg2_kernel<<<(N_NODESK * 32 + 255) / 256, 256>>>(b2, out);
}

// round 13
// speedup vs baseline: 1.6799x; 1.6722x over previous
#include <cuda_runtime.h>
#include <cstdint>
#include <math.h>

#define N_NODESK 50000
#define N_EDGESK 800000
#define F_INK    128
#define C1K      256     // HEADS*HID
#define HEADSK   8
#define NBLK_SCAN 196    // ceil(50000/256)
#define FULLMASK 0xffffffffu

// ---------------- scratch (device globals: allocation-free contract) ----------------
__device__ float g_h1[N_NODESK * C1K];     // x @ W1 (51.2 MB)
__device__ float g_as1[N_NODESK * HEADSK];
__device__ float g_ad1[N_NODESK * HEADSK];
__device__ float g_h2[N_NODESK * 2];
__device__ float g_as2[N_NODESK];
__device__ float g_ad2[N_NODESK];
__device__ int   g_cnt[N_NODESK];
__device__ int   g_rowptr[N_NODESK + 1];
__device__ int   g_cursor[N_NODESK];
__device__ int   g_col[N_EDGESK];          // src ids grouped by dst
__device__ int   g_bsum[NBLK_SCAN];
__device__ int   g_boff[NBLK_SCAN];

// ---------------- CSR build ----------------
__global__ void zero_cnt_kernel() {
    int i = blockIdx.x * blockDim.x + threadIdx.x;
    if (i < N_NODESK) g_cnt[i] = 0;
}

__global__ void hist_kernel(const int* __restrict__ dst) {
    int e = blockIdx.x * blockDim.x + threadIdx.x;
    if (e < N_EDGESK) atomicAdd(&g_cnt[dst[e]], 1);
}

__global__ void blocksum_kernel() {
    int i = blockIdx.x * 256 + threadIdx.x;
    int v = (i < N_NODESK) ? g_cnt[i] : 0;
    __shared__ int ws[8];
    int lane = threadIdx.x & 31, w = threadIdx.x >> 5;
#pragma unroll
    for (int o = 16; o; o >>= 1) v += __shfl_xor_sync(FULLMASK, v, o);
    if (lane == 0) ws[w] = v;
    __syncthreads();
    if (threadIdx.x == 0) {
        int s = 0;
#pragma unroll
        for (int k = 0; k < 8; k++) s += ws[k];
        g_bsum[blockIdx.x] = s;
    }
}

__global__ void scantop_kernel() {
    __shared__ int sh[256];
    int v = (threadIdx.x < NBLK_SCAN) ? g_bsum[threadIdx.x] : 0;
    sh[threadIdx.x] = v;
    __syncthreads();
    for (int off = 1; off < 256; off <<= 1) {
        int t = (threadIdx.x >= off) ? sh[threadIdx.x - off] : 0;
        __syncthreads();
        sh[threadIdx.x] += t;
        __syncthreads();
    }
    if (threadIdx.x < NBLK_SCAN) g_boff[threadIdx.x] = sh[threadIdx.x] - v;
}

__global__ void scanlocal_kernel() {
    __shared__ int sh[256];
    int i = blockIdx.x * 256 + threadIdx.x;
    int v = (i < N_NODESK) ? g_cnt[i] : 0;
    sh[threadIdx.x] = v;
    __syncthreads();
    for (int off = 1; off < 256; off <<= 1) {
        int t = (threadIdx.x >= off) ? sh[threadIdx.x - off] : 0;
        __syncthreads();
        sh[threadIdx.x] += t;
        __syncthreads();
    }
    int incl = sh[threadIdx.x];
    int base = g_boff[blockIdx.x];
    if (i < N_NODESK) {
        int excl = base + incl - v;
        g_rowptr[i] = excl;
        g_cursor[i] = excl;
        if (i == N_NODESK - 1) g_rowptr[N_NODESK] = base + incl;
    }
}

__global__ void scatter_kernel(const int* __restrict__ src, const int* __restrict__ dst) {
    int e = blockIdx.x * blockDim.x + threadIdx.x;
    if (e < N_EDGESK) {
        int pos = atomicAdd(&g_cursor[dst[e]], 1);
        g_col[pos] = src[e];
    }
}

// ---------------- tensor-core SGEMM (3xTF32) + fused alpha1 ----------------
// g_h1 = x[M,128] @ W1[128,256]; also emits g_as1/g_ad1 per (node, head).
// CTA tile 128m x 64n, 8 warps (4 m-warps x 2 n-warps), warp tile 32x32.
// 3xTF32: C += Ahi*Bhi + Ahi*Blo + Alo*Bhi  (error ~1e-7 rel).

__device__ __forceinline__ void tf32_split(float v, unsigned int& hi, unsigned int& lo) {
    asm("cvt.rna.tf32.f32 %0, %1;" : "=r"(hi) : "f"(v));
    float r = v - __uint_as_float(hi);
    asm("cvt.rna.tf32.f32 %0, %1;" : "=r"(lo) : "f"(r));
}

__device__ __forceinline__ void mma_tf32(float* c, const unsigned int* a, const unsigned int* b) {
    asm volatile(
        "mma.sync.aligned.m16n8k8.row.col.f32.tf32.tf32.f32 "
        "{%0,%1,%2,%3}, {%4,%5,%6,%7}, {%8,%9}, {%0,%1,%2,%3};"
        : "+f"(c[0]), "+f"(c[1]), "+f"(c[2]), "+f"(c[3])
        : "r"(a[0]), "r"(a[1]), "r"(a[2]), "r"(a[3]), "r"(b[0]), "r"(b[1]));
}

__global__ __launch_bounds__(256, 2) void sgemm_tc_kernel(const float* __restrict__ A,
                                                          const float* __restrict__ B,
                                                          const float* __restrict__ a1s,
                                                          const float* __restrict__ a1d) {
    __shared__ unsigned int sAh[128][20], sAl[128][20];   // [m][k] k-minor, pad->20
    __shared__ unsigned int sBh[16][72],  sBl[16][72];    // [k][n] n-minor, pad->72

    const int tid  = threadIdx.x;
    const int lane = tid & 31;
    const int wid  = tid >> 5;
    const int g    = lane >> 2;       // 0..7
    const int tg   = lane & 3;        // 0..3
    const int m0   = (wid & 3) * 32;
    const int n0   = (wid >> 2) * 32;
    const int bm   = blockIdx.y * 128;
    const int bn   = blockIdx.x * 64;

    float c[2][4][4];
#pragma unroll
    for (int mi = 0; mi < 2; mi++)
#pragma unroll
        for (int ni = 0; ni < 4; ni++)
#pragma unroll
            for (int q = 0; q < 4; q++) c[mi][ni][q] = 0.f;

    for (int kt = 0; kt < F_INK; kt += 16) {
        // A tile: 128 rows x 16 k = 512 float4; 2 per thread, coalesced.
#pragma unroll
        for (int i = 0; i < 2; i++) {
            int idx = tid + i * 256;
            int row = idx >> 2, kq = idx & 3;
            float4 v = make_float4(0.f, 0.f, 0.f, 0.f);
            int grow = bm + row;
            if (grow < N_NODESK)
                v = *(const float4*)(A + (size_t)grow * F_INK + kt + kq * 4);
            uint4 h, l;
            tf32_split(v.x, h.x, l.x);
            tf32_split(v.y, h.y, l.y);
            tf32_split(v.z, h.z, l.z);
            tf32_split(v.w, h.w, l.w);
            *(uint4*)&sAh[row][kq * 4] = h;
            *(uint4*)&sAl[row][kq * 4] = l;
        }
        // B tile: 16 k x 64 n = 256 float4; 1 per thread.
        {
            int k = tid >> 4, cq = tid & 15;
            float4 v = *(const float4*)(B + (size_t)(kt + k) * C1K + bn + cq * 4);
            uint4 h, l;
            tf32_split(v.x, h.x, l.x);
            tf32_split(v.y, h.y, l.y);
            tf32_split(v.z, h.z, l.z);
            tf32_split(v.w, h.w, l.w);
            *(uint4*)&sBh[k][cq * 4] = h;
            *(uint4*)&sBl[k][cq * 4] = l;
        }
        __syncthreads();
#pragma unroll
        for (int k0 = 0; k0 < 16; k0 += 8) {
            unsigned int ah[2][4], al[2][4], bh[4][2], bl[4][2];
#pragma unroll
            for (int mi = 0; mi < 2; mi++) {
                int r = m0 + mi * 16;
                ah[mi][0] = sAh[r + g][k0 + tg];
                ah[mi][1] = sAh[r + 8 + g][k0 + tg];
                ah[mi][2] = sAh[r + g][k0 + tg + 4];
                ah[mi][3] = sAh[r + 8 + g][k0 + tg + 4];
                al[mi][0] = sAl[r + g][k0 + tg];
                al[mi][1] = sAl[r + 8 + g][k0 + tg];
                al[mi][2] = sAl[r + g][k0 + tg + 4];
                al[mi][3] = sAl[r + 8 + g][k0 + tg + 4];
            }
#pragma unroll
            for (int ni = 0; ni < 4; ni++) {
                int col = n0 + ni * 8 + g;
                bh[ni][0] = sBh[k0 + tg][col];
                bh[ni][1] = sBh[k0 + tg + 4][col];
                bl[ni][0] = sBl[k0 + tg][col];
                bl[ni][1] = sBl[k0 + tg + 4][col];
            }
#pragma unroll
            for (int mi = 0; mi < 2; mi++)
#pragma unroll
                for (int ni = 0; ni < 4; ni++) {
                    mma_tf32(c[mi][ni], ah[mi], bh[ni]);
                    mma_tf32(c[mi][ni], ah[mi], bl[ni]);
                    mma_tf32(c[mi][ni], al[mi], bh[ni]);
                }
        }
        __syncthreads();
    }

    // store C tile
#pragma unroll
    for (int mi = 0; mi < 2; mi++)
#pragma unroll
        for (int ni = 0; ni < 4; ni++) {
            int r = bm + m0 + mi * 16 + g;
            int col = bn + n0 + ni * 8 + tg * 2;
            if (r < N_NODESK)
                *(float2*)(g_h1 + (size_t)r * C1K + col) =
                    make_float2(c[mi][ni][0], c[mi][ni][1]);
            if (r + 8 < N_NODESK)
                *(float2*)(g_h1 + (size_t)(r + 8) * C1K + col) =
                    make_float2(c[mi][ni][2], c[mi][ni][3]);
        }

    // fused alpha1: this warp's 32-col slab == one head
    {
        int hidx = (bn >> 5) + (wid >> 2);
        float s[4] = {0.f, 0.f, 0.f, 0.f};
        float d[4] = {0.f, 0.f, 0.f, 0.f};
#pragma unroll
        for (int ni = 0; ni < 4; ni++) {
            int lc = ni * 8 + tg * 2;
            float as0 = a1s[hidx * 32 + lc], as1 = a1s[hidx * 32 + lc + 1];
            float ad0 = a1d[hidx * 32 + lc], ad1 = a1d[hidx * 32 + lc + 1];
            s[0] += c[0][ni][0] * as0 + c[0][ni][1] * as1;
            s[1] += c[0][ni][2] * as0 + c[0][ni][3] * as1;
            s[2] += c[1][ni][0] * as0 + c[1][ni][1] * as1;
            s[3] += c[1][ni][2] * as0 + c[1][ni][3] * as1;
            d[0] += c[0][ni][0] * ad0 + c[0][ni][1] * ad1;
            d[1] += c[0][ni][2] * ad0 + c[0][ni][3] * ad1;
            d[2] += c[1][ni][0] * ad0 + c[1][ni][1] * ad1;
            d[3] += c[1][ni][2] * ad0 + c[1][ni][3] * ad1;
        }
#pragma unroll
        for (int off = 1; off <= 2; off <<= 1) {
#pragma unroll
            for (int j = 0; j < 4; j++) {
                s[j] += __shfl_xor_sync(FULLMASK, s[j], off);
                d[j] += __shfl_xor_sync(FULLMASK, d[j], off);
            }
        }
        if (tg == 0) {
            int rbase = bm + m0 + g;
#pragma unroll
            for (int j = 0; j < 4; j++) {
                int r = rbase + ((j & 1) ? 8 : 0) + ((j >> 1) ? 16 : 0);
                if (r < N_NODESK) {
                    g_as1[r * 8 + hidx] = s[j];
                    g_ad1[r * 8 + hidx] = d[j];
                }
            }
        }
    }
}

__device__ __forceinline__ float lrelu02(float x) { return x > 0.f ? x : 0.2f * x; }
__device__ __forceinline__ float eluf(float x)    { return x > 0.f ? x : expm1f(x); }

// ---------------- layer-1 aggregation (quad-edge, exp-dedup) fused with layer-2 transform --
__global__ __launch_bounds__(256) void agg1_kernel(const float* __restrict__ b1,
                                                   const float* __restrict__ W2,
                                                   const float* __restrict__ a2s,
                                                   const float* __restrict__ a2d) {
    int warp = (blockIdx.x * blockDim.x + threadIdx.x) >> 5;
    int lane = threadIdx.x & 31;
    if (warp >= N_NODESK) return;
    const int n = warp;
    const int hA = lane >> 3;
    const int hB = 4 + hA;
    const int l7 = lane & 7;
    const int grp = lane >> 3;
    const float ad8 = g_ad1[n * 8 + l7];

    float4 accA = make_float4(0.f, 0.f, 0.f, 0.f);
    float4 accB = make_float4(0.f, 0.f, 0.f, 0.f);
    float denA = 0.f, denB = 0.f;

    const int beg = g_rowptr[n], end = g_rowptr[n + 1];

    {
        float w = __expf(lrelu02(g_as1[n * 8 + l7] + ad8));
        float wA = __shfl_sync(FULLMASK, w, hA);
        float wB = __shfl_sync(FULLMASK, w, hB);
        const float4* row = (const float4*)(g_h1 + (size_t)n * C1K);
        float4 vA = row[lane], vB = row[32 + lane];
        accA.x += wA * vA.x; accA.y += wA * vA.y; accA.z += wA * vA.z; accA.w += wA * vA.w;
        accB.x += wB * vB.x; accB.y += wB * vB.y; accB.z += wB * vB.z; accB.w += wB * vB.w;
        denA += wA; denB += wB;
    }

    int e = beg;
    for (; e + 4 <= end; e += 4) {
        int ss = g_col[e + grp];
        float w = __expf(lrelu02(g_as1[ss * 8 + l7] + ad8));
#pragma unroll
        for (int j = 0; j < 4; ++j) {
            int  sj = __shfl_sync(FULLMASK, ss, j * 8);
            float wA = __shfl_sync(FULLMASK, w, j * 8 + hA);
            float wB = __shfl_sync(FULLMASK, w, j * 8 + hB);
            const float4* row = (const float4*)(g_h1 + (size_t)sj * C1K);
            float4 vA = row[lane], vB = row[32 + lane];
            accA.x += wA * vA.x; accA.y += wA * vA.y; accA.z += wA * vA.z; accA.w += wA * vA.w;
            accB.x += wB * vB.x; accB.y += wB * vB.y; accB.z += wB * vB.z; accB.w += wB * vB.w;
            denA += wA; denB += wB;
        }
    }
    for (; e < end; ++e) {
        int s = g_col[e];
        float w = __expf(lrelu02(g_as1[s * 8 + l7] + ad8));
        float wA = __shfl_sync(FULLMASK, w, hA);
        float wB = __shfl_sync(FULLMASK, w, hB);
        const float4* row = (const float4*)(g_h1 + (size_t)s * C1K);
        float4 vA = row[lane], vB = row[32 + lane];
        accA.x += wA * vA.x; accA.y += wA * vA.y; accA.z += wA * vA.z; accA.w += wA * vA.w;
        accB.x += wB * vB.x; accB.y += wB * vB.y; accB.z += wB * vB.z; accB.w += wB * vB.w;
        denA += wA; denB += wB;
    }

    float rA = 1.f / denA, rB = 1.f / denB;
    const float4 bA = *(const float4*)(b1 + 4 * lane);
    const float4 bB = *(const float4*)(b1 + 128 + 4 * lane);
    float4 oA, oB;
    oA.x = eluf(accA.x * rA + bA.x); oA.y = eluf(accA.y * rA + bA.y);
    oA.z = eluf(accA.z * rA + bA.z); oA.w = eluf(accA.w * rA + bA.w);
    oB.x = eluf(accB.x * rB + bB.x); oB.y = eluf(accB.y * rB + bB.y);
    oB.z = eluf(accB.z * rB + bB.z); oB.w = eluf(accB.w * rB + bB.w);

    int cA = 4 * lane, cB = 128 + 4 * lane;
    float acc0 = oA.x * W2[(cA + 0) * 2] + oA.y * W2[(cA + 1) * 2]
               + oA.z * W2[(cA + 2) * 2] + oA.w * W2[(cA + 3) * 2]
               + oB.x * W2[(cB + 0) * 2] + oB.y * W2[(cB + 1) * 2]
               + oB.z * W2[(cB + 2) * 2] + oB.w * W2[(cB + 3) * 2];
    float acc1 = oA.x * W2[(cA + 0) * 2 + 1] + oA.y * W2[(cA + 1) * 2 + 1]
               + oA.z * W2[(cA + 2) * 2 + 1] + oA.w * W2[(cA + 3) * 2 + 1]
               + oB.x * W2[(cB + 0) * 2 + 1] + oB.y * W2[(cB + 1) * 2 + 1]
               + oB.z * W2[(cB + 2) * 2 + 1] + oB.w * W2[(cB + 3) * 2 + 1];
#pragma unroll
    for (int o = 16; o; o >>= 1) {
        acc0 += __shfl_xor_sync(FULLMASK, acc0, o);
        acc1 += __shfl_xor_sync(FULLMASK, acc1, o);
    }
    if (lane == 0) {
        g_h2[n * 2 + 0] = acc0;
        g_h2[n * 2 + 1] = acc1;
        g_as2[n] = acc0 * a2s[0] + acc1 * a2s[1];
        g_ad2[n] = acc0 * a2d[0] + acc1 * a2d[1];
    }
}

// ---------------- layer-2 aggregation: warp per dst node (edge-parallel) ----------------
__global__ __launch_bounds__(256) void agg2_kernel(const float* __restrict__ b2,
                                                   float* __restrict__ out) {
    int warp = (blockIdx.x * blockDim.x + threadIdx.x) >> 5;
    int lane = threadIdx.x & 31;
    if (warp >= N_NODESK) return;
    const int n = warp;
    float adn = g_ad2[n];
    int beg = g_rowptr[n], end = g_rowptr[n + 1];
    float den = 0.f, o0 = 0.f, o1 = 0.f;
    for (int e = beg + lane; e < end; e += 32) {
        int s = g_col[e];
        float w = __expf(lrelu02(g_as2[s] + adn));
        den += w;
        o0 += w * g_h2[s * 2 + 0];
        o1 += w * g_h2[s * 2 + 1];
    }
    if (lane == 0) {
        float w = __expf(lrelu02(g_as2[n] + adn));
        den += w;
        o0 += w * g_h2[n * 2 + 0];
        o1 += w * g_h2[n * 2 + 1];
    }
#pragma unroll
    for (int o = 16; o; o >>= 1) {
        den += __shfl_xor_sync(FULLMASK, den, o);
        o0  += __shfl_xor_sync(FULLMASK, o0, o);
        o1  += __shfl_xor_sync(FULLMASK, o1, o);
    }
    if (lane == 0) {
        float r = 1.f / den;
        out[n * 2 + 0] = o0 * r + b2[0];
        out[n * 2 + 1] = o1 * r + b2[1];
    }
}

// ---------------- launch ----------------
extern "C" void kernel_launch(void* const* d_in, const int* in_sizes, int n_in,
                              void* d_out, int out_size) {
    const float* x    = (const float*)d_in[0];
    const int*   ei   = (const int*)d_in[1];
    const float* W1   = (const float*)d_in[3];
    const float* a1s  = (const float*)d_in[4];
    const float* a1d  = (const float*)d_in[5];
    const float* b1   = (const float*)d_in[6];
    const float* W2   = (const float*)d_in[7];
    const float* a2s  = (const float*)d_in[8];
    const float* a2d  = (const float*)d_in[9];
    const float* b2   = (const float*)d_in[10];
    float* out = (float*)d_out;

    const int* src = ei;
    const int* dst = ei + N_EDGESK;

    zero_cnt_kernel<<<(N_NODESK + 255) / 256, 256>>>();
    hist_kernel<<<(N_EDGESK + 255) / 256, 256>>>(dst);
    blocksum_kernel<<<NBLK_SCAN, 256>>>();
    scantop_kernel<<<1, 256>>>();
    scanlocal_kernel<<<NBLK_SCAN, 256>>>();
    sgemm_tc_kernel<<<dim3(C1K / 64, (N_NODESK + 127) / 128), 256>>>(x, W1, a1s, a1d);
    scatter_kernel<<<(N_EDGESK + 255) / 256, 256>>>(src, dst);

    agg1_kernel<<<(N_NODESK * 32 + 255) / 256, 256>>>(b1, W2, a2s, a2d);
    agg2_kernel<<<(N_NODESK * 32 + 255) / 256, 256>>>(b2, out);
}

// round 14
// speedup vs baseline: 1.7868x; 1.0636x over previous
#include <cuda_runtime.h>
#include <cuda_fp16.h>
#include <cstdint>
#include <math.h>

#define N_NODESK 50000
#define N_EDGESK 800000
#define F_INK    128
#define C1K      256     // HEADS*HID
#define HEADSK   8
#define NBLK_SCAN 196    // ceil(50000/256)
#define FULLMASK 0xffffffffu

// ---------------- scratch (device globals: allocation-free contract) ----------------
__device__ __half2 g_h1h[N_NODESK * 128];  // h1 in fp16 (half2 pairs), 25.6 MB
__device__ float g_as1[N_NODESK * HEADSK];
__device__ float g_ad1[N_NODESK * HEADSK];
__device__ float g_h2[N_NODESK * 2];
__device__ float g_as2[N_NODESK];
__device__ float g_ad2[N_NODESK];
__device__ int   g_cnt[N_NODESK];
__device__ int   g_rowptr[N_NODESK + 1];
__device__ int   g_cursor[N_NODESK];
__device__ int   g_col[N_EDGESK];          // src ids grouped by dst
__device__ int   g_bsum[NBLK_SCAN];
__device__ int   g_boff[NBLK_SCAN];

// ---------------- CSR build ----------------
__global__ void zero_cnt_kernel() {
    int i = blockIdx.x * blockDim.x + threadIdx.x;
    if (i < N_NODESK) g_cnt[i] = 0;
}

__global__ void hist_kernel(const int* __restrict__ dst) {
    int e = blockIdx.x * blockDim.x + threadIdx.x;
    if (e < N_EDGESK) atomicAdd(&g_cnt[dst[e]], 1);
}

__global__ void blocksum_kernel() {
    int i = blockIdx.x * 256 + threadIdx.x;
    int v = (i < N_NODESK) ? g_cnt[i] : 0;
    __shared__ int ws[8];
    int lane = threadIdx.x & 31, w = threadIdx.x >> 5;
#pragma unroll
    for (int o = 16; o; o >>= 1) v += __shfl_xor_sync(FULLMASK, v, o);
    if (lane == 0) ws[w] = v;
    __syncthreads();
    if (threadIdx.x == 0) {
        int s = 0;
#pragma unroll
        for (int k = 0; k < 8; k++) s += ws[k];
        g_bsum[blockIdx.x] = s;
    }
}

__global__ void scantop_kernel() {
    __shared__ int sh[256];
    int v = (threadIdx.x < NBLK_SCAN) ? g_bsum[threadIdx.x] : 0;
    sh[threadIdx.x] = v;
    __syncthreads();
    for (int off = 1; off < 256; off <<= 1) {
        int t = (threadIdx.x >= off) ? sh[threadIdx.x - off] : 0;
        __syncthreads();
        sh[threadIdx.x] += t;
        __syncthreads();
    }
    if (threadIdx.x < NBLK_SCAN) g_boff[threadIdx.x] = sh[threadIdx.x] - v;
}

__global__ void scanlocal_kernel() {
    __shared__ int sh[256];
    int i = blockIdx.x * 256 + threadIdx.x;
    int v = (i < N_NODESK) ? g_cnt[i] : 0;
    sh[threadIdx.x] = v;
    __syncthreads();
    for (int off = 1; off < 256; off <<= 1) {
        int t = (threadIdx.x >= off) ? sh[threadIdx.x - off] : 0;
        __syncthreads();
        sh[threadIdx.x] += t;
        __syncthreads();
    }
    int incl = sh[threadIdx.x];
    int base = g_boff[blockIdx.x];
    if (i < N_NODESK) {
        int excl = base + incl - v;
        g_rowptr[i] = excl;
        g_cursor[i] = excl;
        if (i == N_NODESK - 1) g_rowptr[N_NODESK] = base + incl;
    }
}

__global__ void scatter_kernel(const int* __restrict__ src, const int* __restrict__ dst) {
    int e = blockIdx.x * blockDim.x + threadIdx.x;
    if (e < N_EDGESK) {
        int pos = atomicAdd(&g_cursor[dst[e]], 1);
        g_col[pos] = src[e];
    }
}

// ---------------- tensor-core SGEMM (3xTF32) + fused alpha1, fp16 h1 output ----------
__device__ __forceinline__ void tf32_split(float v, unsigned int& hi, unsigned int& lo) {
    asm("cvt.rna.tf32.f32 %0, %1;" : "=r"(hi) : "f"(v));
    float r = v - __uint_as_float(hi);
    asm("cvt.rna.tf32.f32 %0, %1;" : "=r"(lo) : "f"(r));
}

__device__ __forceinline__ void mma_tf32(float* c, const unsigned int* a, const unsigned int* b) {
    asm volatile(
        "mma.sync.aligned.m16n8k8.row.col.f32.tf32.tf32.f32 "
        "{%0,%1,%2,%3}, {%4,%5,%6,%7}, {%8,%9}, {%0,%1,%2,%3};"
        : "+f"(c[0]), "+f"(c[1]), "+f"(c[2]), "+f"(c[3])
        : "r"(a[0]), "r"(a[1]), "r"(a[2]), "r"(a[3]), "r"(b[0]), "r"(b[1]));
}

__global__ __launch_bounds__(256, 2) void sgemm_tc_kernel(const float* __restrict__ A,
                                                          const float* __restrict__ B,
                                                          const float* __restrict__ a1s,
                                                          const float* __restrict__ a1d) {
    __shared__ unsigned int sAh[128][20], sAl[128][20];   // [m][k] k-minor, pad->20
    __shared__ unsigned int sBh[16][72],  sBl[16][72];    // [k][n] n-minor, pad->72

    const int tid  = threadIdx.x;
    const int lane = tid & 31;
    const int wid  = tid >> 5;
    const int g    = lane >> 2;       // 0..7
    const int tg   = lane & 3;        // 0..3
    const int m0   = (wid & 3) * 32;
    const int n0   = (wid >> 2) * 32;
    const int bm   = blockIdx.y * 128;
    const int bn   = blockIdx.x * 64;

    float c[2][4][4];
#pragma unroll
    for (int mi = 0; mi < 2; mi++)
#pragma unroll
        for (int ni = 0; ni < 4; ni++)
#pragma unroll
            for (int q = 0; q < 4; q++) c[mi][ni][q] = 0.f;

    for (int kt = 0; kt < F_INK; kt += 16) {
#pragma unroll
        for (int i = 0; i < 2; i++) {
            int idx = tid + i * 256;
            int row = idx >> 2, kq = idx & 3;
            float4 v = make_float4(0.f, 0.f, 0.f, 0.f);
            int grow = bm + row;
            if (grow < N_NODESK)
                v = *(const float4*)(A + (size_t)grow * F_INK + kt + kq * 4);
            uint4 h, l;
            tf32_split(v.x, h.x, l.x);
            tf32_split(v.y, h.y, l.y);
            tf32_split(v.z, h.z, l.z);
            tf32_split(v.w, h.w, l.w);
            *(uint4*)&sAh[row][kq * 4] = h;
            *(uint4*)&sAl[row][kq * 4] = l;
        }
        {
            int k = tid >> 4, cq = tid & 15;
            float4 v = *(const float4*)(B + (size_t)(kt + k) * C1K + bn + cq * 4);
            uint4 h, l;
            tf32_split(v.x, h.x, l.x);
            tf32_split(v.y, h.y, l.y);
            tf32_split(v.z, h.z, l.z);
            tf32_split(v.w, h.w, l.w);
            *(uint4*)&sBh[k][cq * 4] = h;
            *(uint4*)&sBl[k][cq * 4] = l;
        }
        __syncthreads();
#pragma unroll
        for (int k0 = 0; k0 < 16; k0 += 8) {
            unsigned int ah[2][4], al[2][4], bh[4][2], bl[4][2];
#pragma unroll
            for (int mi = 0; mi < 2; mi++) {
                int r = m0 + mi * 16;
                ah[mi][0] = sAh[r + g][k0 + tg];
                ah[mi][1] = sAh[r + 8 + g][k0 + tg];
                ah[mi][2] = sAh[r + g][k0 + tg + 4];
                ah[mi][3] = sAh[r + 8 + g][k0 + tg + 4];
                al[mi][0] = sAl[r + g][k0 + tg];
                al[mi][1] = sAl[r + 8 + g][k0 + tg];
                al[mi][2] = sAl[r + g][k0 + tg + 4];
                al[mi][3] = sAl[r + 8 + g][k0 + tg + 4];
            }
#pragma unroll
            for (int ni = 0; ni < 4; ni++) {
                int col = n0 + ni * 8 + g;
                bh[ni][0] = sBh[k0 + tg][col];
                bh[ni][1] = sBh[k0 + tg + 4][col];
                bl[ni][0] = sBl[k0 + tg][col];
                bl[ni][1] = sBl[k0 + tg + 4][col];
            }
#pragma unroll
            for (int mi = 0; mi < 2; mi++)
#pragma unroll
                for (int ni = 0; ni < 4; ni++) {
                    mma_tf32(c[mi][ni], ah[mi], bh[ni]);
                    mma_tf32(c[mi][ni], ah[mi], bl[ni]);
                    mma_tf32(c[mi][ni], al[mi], bh[ni]);
                }
        }
        __syncthreads();
    }

    // store C tile as fp16 (half2 per channel pair)
#pragma unroll
    for (int mi = 0; mi < 2; mi++)
#pragma unroll
        for (int ni = 0; ni < 4; ni++) {
            int r = bm + m0 + mi * 16 + g;
            int col = bn + n0 + ni * 8 + tg * 2;   // even
            if (r < N_NODESK)
                g_h1h[(size_t)r * 128 + (col >> 1)] =
                    __floats2half2_rn(c[mi][ni][0], c[mi][ni][1]);
            if (r + 8 < N_NODESK)
                g_h1h[(size_t)(r + 8) * 128 + (col >> 1)] =
                    __floats2half2_rn(c[mi][ni][2], c[mi][ni][3]);
        }

    // fused alpha1 from fp32 accumulators: this warp's 32-col slab == one head
    {
        int hidx = (bn >> 5) + (wid >> 2);
        float s[4] = {0.f, 0.f, 0.f, 0.f};
        float d[4] = {0.f, 0.f, 0.f, 0.f};
#pragma unroll
        for (int ni = 0; ni < 4; ni++) {
            int lc = ni * 8 + tg * 2;
            float as0 = a1s[hidx * 32 + lc], as1 = a1s[hidx * 32 + lc + 1];
            float ad0 = a1d[hidx * 32 + lc], ad1 = a1d[hidx * 32 + lc + 1];
            s[0] += c[0][ni][0] * as0 + c[0][ni][1] * as1;
            s[1] += c[0][ni][2] * as0 + c[0][ni][3] * as1;
            s[2] += c[1][ni][0] * as0 + c[1][ni][1] * as1;
            s[3] += c[1][ni][2] * as0 + c[1][ni][3] * as1;
            d[0] += c[0][ni][0] * ad0 + c[0][ni][1] * ad1;
            d[1] += c[0][ni][2] * ad0 + c[0][ni][3] * ad1;
            d[2] += c[1][ni][0] * ad0 + c[1][ni][1] * ad1;
            d[3] += c[1][ni][2] * ad0 + c[1][ni][3] * ad1;
        }
#pragma unroll
        for (int off = 1; off <= 2; off <<= 1) {
#pragma unroll
            for (int j = 0; j < 4; j++) {
                s[j] += __shfl_xor_sync(FULLMASK, s[j], off);
                d[j] += __shfl_xor_sync(FULLMASK, d[j], off);
            }
        }
        if (tg == 0) {
            int rbase = bm + m0 + g;
#pragma unroll
            for (int j = 0; j < 4; j++) {
                int r = rbase + ((j & 1) ? 8 : 0) + ((j >> 1) ? 16 : 0);
                if (r < N_NODESK) {
                    g_as1[r * 8 + hidx] = s[j];
                    g_ad1[r * 8 + hidx] = d[j];
                }
            }
        }
    }
}

__device__ __forceinline__ float lrelu02(float x) { return x > 0.f ? x : 0.2f * x; }
__device__ __forceinline__ float eluf(float x)    { return x > 0.f ? x : expm1f(x); }

// accumulate 4 fp16 channels (one uint2 = 2 half2) into fp32 acc with weight w
__device__ __forceinline__ void acc_h4(float4& acc, uint2 p, float w) {
    float2 a = __half22float2(*(__half2*)&p.x);
    float2 b = __half22float2(*(__half2*)&p.y);
    acc.x += w * a.x; acc.y += w * a.y;
    acc.z += w * b.x; acc.w += w * b.y;
}

// ---------------- layer-1 aggregation (quad-edge, exp-dedup, fp16 gather) + layer-2 fuse --
__global__ __launch_bounds__(256) void agg1_kernel(const float* __restrict__ b1,
                                                   const float* __restrict__ W2,
                                                   const float* __restrict__ a2s,
                                                   const float* __restrict__ a2d) {
    int warp = (blockIdx.x * blockDim.x + threadIdx.x) >> 5;
    int lane = threadIdx.x & 31;
    if (warp >= N_NODESK) return;
    const int n = warp;
    const int hA = lane >> 3;
    const int hB = 4 + hA;
    const int l7 = lane & 7;
    const int grp = lane >> 3;
    const float ad8 = g_ad1[n * 8 + l7];

    float4 accA = make_float4(0.f, 0.f, 0.f, 0.f);
    float4 accB = make_float4(0.f, 0.f, 0.f, 0.f);
    float denA = 0.f, denB = 0.f;

    const int beg = g_rowptr[n], end = g_rowptr[n + 1];

    {   // self loop
        float w = __expf(lrelu02(g_as1[n * 8 + l7] + ad8));
        float wA = __shfl_sync(FULLMASK, w, hA);
        float wB = __shfl_sync(FULLMASK, w, hB);
        const uint2* row = (const uint2*)(g_h1h + (size_t)n * 128);
        acc_h4(accA, row[lane], wA);
        acc_h4(accB, row[32 + lane], wB);
        denA += wA; denB += wB;
    }

    int e = beg;
    for (; e + 4 <= end; e += 4) {
        int ss = g_col[e + grp];
        float w = __expf(lrelu02(g_as1[ss * 8 + l7] + ad8));
#pragma unroll
        for (int j = 0; j < 4; ++j) {
            int  sj = __shfl_sync(FULLMASK, ss, j * 8);
            float wA = __shfl_sync(FULLMASK, w, j * 8 + hA);
            float wB = __shfl_sync(FULLMASK, w, j * 8 + hB);
            const uint2* row = (const uint2*)(g_h1h + (size_t)sj * 128);
            acc_h4(accA, row[lane], wA);
            acc_h4(accB, row[32 + lane], wB);
            denA += wA; denB += wB;
        }
    }
    for (; e < end; ++e) {
        int s = g_col[e];
        float w = __expf(lrelu02(g_as1[s * 8 + l7] + ad8));
        float wA = __shfl_sync(FULLMASK, w, hA);
        float wB = __shfl_sync(FULLMASK, w, hB);
        const uint2* row = (const uint2*)(g_h1h + (size_t)s * 128);
        acc_h4(accA, row[lane], wA);
        acc_h4(accB, row[32 + lane], wB);
        denA += wA; denB += wB;
    }

    float rA = 1.f / denA, rB = 1.f / denB;
    const float4 bA = *(const float4*)(b1 + 4 * lane);
    const float4 bB = *(const float4*)(b1 + 128 + 4 * lane);
    float4 oA, oB;
    oA.x = eluf(accA.x * rA + bA.x); oA.y = eluf(accA.y * rA + bA.y);
    oA.z = eluf(accA.z * rA + bA.z); oA.w = eluf(accA.w * rA + bA.w);
    oB.x = eluf(accB.x * rB + bB.x); oB.y = eluf(accB.y * rB + bB.y);
    oB.z = eluf(accB.z * rB + bB.z); oB.w = eluf(accB.w * rB + bB.w);

    int cA = 4 * lane, cB = 128 + 4 * lane;
    float acc0 = oA.x * W2[(cA + 0) * 2] + oA.y * W2[(cA + 1) * 2]
               + oA.z * W2[(cA + 2) * 2] + oA.w * W2[(cA + 3) * 2]
               + oB.x * W2[(cB + 0) * 2] + oB.y * W2[(cB + 1) * 2]
               + oB.z * W2[(cB + 2) * 2] + oB.w * W2[(cB + 3) * 2];
    float acc1 = oA.x * W2[(cA + 0) * 2 + 1] + oA.y * W2[(cA + 1) * 2 + 1]
               + oA.z * W2[(cA + 2) * 2 + 1] + oA.w * W2[(cA + 3) * 2 + 1]
               + oB.x * W2[(cB + 0) * 2 + 1] + oB.y * W2[(cB + 1) * 2 + 1]
               + oB.z * W2[(cB + 2) * 2 + 1] + oB.w * W2[(cB + 3) * 2 + 1];
#pragma unroll
    for (int o = 16; o; o >>= 1) {
        acc0 += __shfl_xor_sync(FULLMASK, acc0, o);
        acc1 += __shfl_xor_sync(FULLMASK, acc1, o);
    }
    if (lane == 0) {
        g_h2[n * 2 + 0] = acc0;
        g_h2[n * 2 + 1] = acc1;
        g_as2[n] = acc0 * a2s[0] + acc1 * a2s[1];
        g_ad2[n] = acc0 * a2d[0] + acc1 * a2d[1];
    }
}

// ---------------- layer-2 aggregation: warp per dst node (edge-parallel) ----------------
__global__ __launch_bounds__(256) void agg2_kernel(const float* __restrict__ b2,
                                                   float* __restrict__ out) {
    int warp = (blockIdx.x * blockDim.x + threadIdx.x) >> 5;
    int lane = threadIdx.x & 31;
    if (warp >= N_NODESK) return;
    const int n = warp;
    float adn = g_ad2[n];
    int beg = g_rowptr[n], end = g_rowptr[n + 1];
    float den = 0.f, o0 = 0.f, o1 = 0.f;
    for (int e = beg + lane; e < end; e += 32) {
        int s = g_col[e];
        float w = __expf(lrelu02(g_as2[s] + adn));
        den += w;
        o0 += w * g_h2[s * 2 + 0];
        o1 += w * g_h2[s * 2 + 1];
    }
    if (lane == 0) {
        float w = __expf(lrelu02(g_as2[n] + adn));
        den += w;
        o0 += w * g_h2[n * 2 + 0];
        o1 += w * g_h2[n * 2 + 1];
    }
#pragma unroll
    for (int o = 16; o; o >>= 1) {
        den += __shfl_xor_sync(FULLMASK, den, o);
        o0  += __shfl_xor_sync(FULLMASK, o0, o);
        o1  += __shfl_xor_sync(FULLMASK, o1, o);
    }
    if (lane == 0) {
        float r = 1.f / den;
        out[n * 2 + 0] = o0 * r + b2[0];
        out[n * 2 + 1] = o1 * r + b2[1];
    }
}

// ---------------- launch ----------------
extern "C" void kernel_launch(void* const* d_in, const int* in_sizes, int n_in,
                              void* d_out, int out_size) {
    const float* x    = (const float*)d_in[0];
    const int*   ei   = (const int*)d_in[1];
    const float* W1   = (const float*)d_in[3];
    const float* a1s  = (const float*)d_in[4];
    const float* a1d  = (const float*)d_in[5];
    const float* b1   = (const float*)d_in[6];
    const float* W2   = (const float*)d_in[7];
    const float* a2s  = (const float*)d_in[8];
    const float* a2d  = (const float*)d_in[9];
    const float* b2   = (const float*)d_in[10];
    float* out = (float*)d_out;

    const int* src = ei;
    const int* dst = ei + N_EDGESK;

    zero_cnt_kernel<<<(N_NODESK + 255) / 256, 256>>>();
    hist_kernel<<<(N_EDGESK + 255) / 256, 256>>>(dst);
    blocksum_kernel<<<NBLK_SCAN, 256>>>();
    scantop_kernel<<<1, 256>>>();
    scanlocal_kernel<<<NBLK_SCAN, 256>>>();
    sgemm_tc_kernel<<<dim3(C1K / 64, (N_NODESK + 127) / 128), 256>>>(x, W1, a1s, a1d);
    scatter_kernel<<<(N_EDGESK + 255) / 256, 256>>>(src, dst);

    agg1_kernel<<<(N_NODESK * 32 + 255) / 256, 256>>>(b1, W2, a2s, a2d);
    agg2_kernel<<<(N_NODESK * 32 + 255) / 256, 256>>>(b2, out);
}